// round 8
// baseline (speedup 1.0000x reference)
#include <cuda_runtime.h>
#include <cuda_bf16.h>
#include <cstddef>
#include <cstdint>

#define DIMN   512
#define NSLOT  32
#define BATCH  32
#define TSTEPS 2048
#define RANKS  8      // cluster size = d-chunks
#define BPC    4      // batches per CTA
#define DCH    64     // d columns per CTA
#define NTHR   512

// ---------------- scratch ----------------
__device__ float g_pre[(size_t)BATCH * TSTEPS * DIMN];
__device__ float g_WhP[DIMN * DIMN];   // packed: float4 idx = k4*DIMN + d
__device__ float g_WwP[DIMN * DIMN];

// ---------------- PTX helpers ----------------
__device__ __forceinline__ uint32_t smem_u32(const void* p) {
    uint32_t a;
    asm("{ .reg .u64 t; cvta.to.shared.u64 t, %1; cvt.u32.u64 %0, t; }"
        : "=r"(a) : "l"(p));
    return a;
}
__device__ __forceinline__ uint32_t mapa_rank(uint32_t laddr, uint32_t rank) {
    uint32_t r;
    asm("mapa.shared::cluster.u32 %0, %1, %2;" : "=r"(r) : "r"(laddr), "r"(rank));
    return r;
}
__device__ __forceinline__ void sts_cluster_f32(uint32_t addr, float v) {
    asm volatile("st.shared::cluster.f32 [%0], %1;" :: "r"(addr), "f"(v) : "memory");
}
__device__ __forceinline__ void sts_cluster_f32x2(uint32_t addr, float a, float b) {
    asm volatile("st.shared::cluster.v2.f32 [%0], {%1, %2};"
                 :: "r"(addr), "f"(a), "f"(b) : "memory");
}
__device__ __forceinline__ void mbar_init(uint32_t addr, uint32_t cnt) {
    asm volatile("mbarrier.init.shared.b64 [%0], %1;" :: "r"(addr), "r"(cnt) : "memory");
}
__device__ __forceinline__ void mbar_arrive_cl(uint32_t remAddr) {
    asm volatile("mbarrier.arrive.release.cluster.shared::cluster.b64 _, [%0];"
                 :: "r"(remAddr) : "memory");
}
__device__ __forceinline__ void mbar_wait_parity_cl(uint32_t addr, uint32_t parity) {
    asm volatile(
        "{\n\t"
        ".reg .pred P;\n\t"
        "LAB_WAIT_%=:\n\t"
        "mbarrier.try_wait.parity.acquire.cluster.shared::cta.b64 P, [%0], %1, 0x989680;\n\t"
        "@P bra.uni LAB_DONE_%=;\n\t"
        "bra.uni LAB_WAIT_%=;\n\t"
        "LAB_DONE_%=:\n\t"
        "}"
        :: "r"(addr), "r"(parity) : "memory");
}
__device__ __forceinline__ void cluster_sync_() {
    asm volatile("barrier.cluster.arrive.aligned;\n\tbarrier.cluster.wait.aligned;" ::: "memory");
}

// ---------------- weight packing ----------------
__global__ void pack_weights(const float* __restrict__ Wh,
                             const float* __restrict__ Ww) {
    int idx = blockIdx.x * blockDim.x + threadIdx.x;
    if (idx >= DIMN * DIMN) return;
    int d = idx / DIMN;
    int k = idx % DIMN;
    int dst = ((k >> 2) * DIMN + d) * 4 + (k & 3);
    g_WhP[dst] = Wh[idx];
    g_WwP[dst] = Ww[idx];
}

// ---------------- pre-GEMM ----------------
__global__ __launch_bounds__(256) void gemm_pre(
    const float* __restrict__ X,
    const float* __restrict__ W,
    const float* __restrict__ bias)
{
    __shared__ float As[8][128];
    __shared__ float Bs[8][64];

    const int tid = threadIdx.x;
    const int m0 = blockIdx.y * 128;
    const int n0 = blockIdx.x * 64;
    const int trow = tid >> 4;
    const int tcol = tid & 15;

    float acc[8][4];
#pragma unroll
    for (int i = 0; i < 8; ++i)
#pragma unroll
        for (int j = 0; j < 4; ++j) acc[i][j] = 0.f;

    const int a_m  = tid >> 1;
    const int a_k4 = (tid & 1) * 4;

    for (int k0 = 0; k0 < DIMN; k0 += 8) {
        float4 av = *reinterpret_cast<const float4*>(
            X + (size_t)(m0 + a_m) * DIMN + k0 + a_k4);
        As[a_k4 + 0][a_m] = av.x;
        As[a_k4 + 1][a_m] = av.y;
        As[a_k4 + 2][a_m] = av.z;
        As[a_k4 + 3][a_m] = av.w;
        if (tid < 128) {
            int bn  = tid >> 1;
            int bk4 = (tid & 1) * 4;
            float4 bv = *reinterpret_cast<const float4*>(
                W + (size_t)(n0 + bn) * DIMN + k0 + bk4);
            Bs[bk4 + 0][bn] = bv.x;
            Bs[bk4 + 1][bn] = bv.y;
            Bs[bk4 + 2][bn] = bv.z;
            Bs[bk4 + 3][bn] = bv.w;
        }
        __syncthreads();
#pragma unroll
        for (int kk = 0; kk < 8; ++kk) {
            float4 ra0 = *reinterpret_cast<const float4*>(&As[kk][trow * 8]);
            float4 ra1 = *reinterpret_cast<const float4*>(&As[kk][trow * 8 + 4]);
            float4 rb  = *reinterpret_cast<const float4*>(&Bs[kk][tcol * 4]);
            float ra[8] = {ra0.x, ra0.y, ra0.z, ra0.w, ra1.x, ra1.y, ra1.z, ra1.w};
            float rbv[4] = {rb.x, rb.y, rb.z, rb.w};
#pragma unroll
            for (int i = 0; i < 8; ++i)
#pragma unroll
                for (int j = 0; j < 4; ++j) acc[i][j] += ra[i] * rbv[j];
        }
        __syncthreads();
    }

    float4 bj = *reinterpret_cast<const float4*>(bias + n0 + tcol * 4);
#pragma unroll
    for (int i = 0; i < 8; ++i) {
        float4 v;
        v.x = acc[i][0] + bj.x;
        v.y = acc[i][1] + bj.y;
        v.z = acc[i][2] + bj.z;
        v.w = acc[i][3] + bj.w;
        *reinterpret_cast<float4*>(
            &g_pre[(size_t)(m0 + trow * 8 + i) * DIMN + n0 + tcol * 4]) = v;
    }
}

// ---------------- exact entmax-1.5 (warp-collective, lane = slot) ----------------
__device__ __forceinline__ float entmax_coef(float raw, float* __restrict__ sb, int lane) {
    const unsigned FULL = 0xffffffffu;
    float z = raw * 0.5f;
    float m = z;
#pragma unroll
    for (int o = 16; o > 0; o >>= 1) m = fmaxf(m, __shfl_xor_sync(FULL, m, o));
    z -= m;

    int rank = 0;
#pragma unroll
    for (int j = 0; j < 32; ++j) {
        float zj = __shfl_sync(FULL, z, j);
        rank += (zj > z) || (zj == z && j < lane);
    }
    sb[rank] = z;
    __syncwarp();
    float zs = sb[lane];

    float cs = zs, cq = zs * zs;
#pragma unroll
    for (int o = 1; o < 32; o <<= 1) {
        float a  = __shfl_up_sync(FULL, cs, o);
        float bq = __shfl_up_sync(FULL, cq, o);
        if (lane >= o) { cs += a; cq += bq; }
    }
    float k    = (float)(lane + 1);
    float mean = cs / k;
    float msq  = cq / k;
    float ss   = k * (msq - mean * mean);
    float delta = fmaxf((1.f - ss) / k, 0.f);
    float tau   = mean - sqrtf(delta);

    unsigned sup = __ballot_sync(FULL, tau <= zs);
    int kstar = __popc(sup) - 1;
    float tau_star = __shfl_sync(FULL, tau, kstar);
    float p = fmaxf(z - tau_star, 0.f);
    return p * p;
}

// ---------------- SMEM float offsets ----------------
#define SM_WSM    0       // W_h slice [128 k4][64 dl] float4   32768
#define SM_PARTH  32768   // [8][4][64]                          2048
#define SM_PARTW  34816   // [8][4][64]                          2048
#define SM_XW     36864   // [2][4][512]                         4096
#define SM_WVEC   40960   // [4][64]                             256
#define SM_COEFA  41216   // [4][32]                             128
#define SM_COEFB  41344   // [4][32]                             128
#define SM_SORT   41472   // [4][32]                             128
#define SM_TAPE   41600   // [4][32][65]                         8320
#define SM_XC     49920   // [2][8][4][66]                       4224
#define SM_MBARB  54144   // u64
#define SM_MBARC  54146   // u64
#define SM_FLOATS 54148

// ---------------- persistent recurrence ----------------
__global__ void __launch_bounds__(NTHR, 1) __cluster_dims__(RANKS, 1, 1)
recur8(const float* __restrict__ tape0,
       const float* __restrict__ work0,
       float* __restrict__ out_hseq,
       float* __restrict__ out_tape,
       float* __restrict__ out_hlast)
{
    extern __shared__ float sm[];
    float* wsm    = sm + SM_WSM;
    float* part_h = sm + SM_PARTH;
    float* part_w = sm + SM_PARTW;
    float* xw     = sm + SM_XW;
    float* wvec   = sm + SM_WVEC;
    float* coefA  = sm + SM_COEFA;
    float* coefB  = sm + SM_COEFB;
    float* sortb  = sm + SM_SORT;
    float* tape   = sm + SM_TAPE;
    float* xc     = sm + SM_XC;

    const int tid  = threadIdx.x;
    const int lane = tid & 31;
    const int wid  = tid >> 5;
    const int rk   = blockIdx.x & (RANKS - 1);
    const int bg   = blockIdx.x >> 3;
    const int b0   = bg * BPC;
    const int dbase = rk * DCH;

    const uint32_t sbase = smem_u32(sm);
    const uint32_t a_xw  = sbase + SM_XW * 4u;
    const uint32_t a_xc  = sbase + SM_XC * 4u;
    const uint32_t a_mbB = sbase + SM_MBARB * 4u;
    const uint32_t a_mbC = sbase + SM_MBARC * 4u;

    if (tid == 0) {
        mbar_init(a_mbB, RANKS * 8);   // per-warp arrives: 8 warps x 8 CTAs
        mbar_init(a_mbC, RANKS * 4);   // 4 warps x 8 CTAs
    }

    // ---- prologue: tape slice, work0, W_h slice into smem ----
    for (int i = tid; i < BPC * NSLOT * DCH; i += NTHR) {
        int b = i >> 11;
        int n = (i >> 6) & 31;
        int d = i & 63;
        tape[(b * NSLOT + n) * 65 + d] =
            tape0[((size_t)(b0 + b) * NSLOT + n) * DIMN + dbase + d];
    }
    for (int i = tid; i < BPC * DIMN; i += NTHR) {
        int b = i >> 9;
        int k = i & 511;
        xw[b * DIMN + k] = work0[(size_t)(b0 + b) * DIMN + k];
    }
    {
        float4* wsm4 = reinterpret_cast<float4*>(wsm);
        const float4* src = reinterpret_cast<const float4*>(g_WhP);
        for (int i = tid; i < 8192; i += NTHR) {
            int k4 = i >> 6;
            int dl = i & 63;
            wsm4[i] = src[(size_t)k4 * DIMN + dbase + dl];
        }
    }
    __syncthreads();
    cluster_sync_();

    const float invsd = 0.044194173824159216f;  // 1/sqrt(512)

    // ---- initial read-scores exchange (parity 0), per-warp arrives ----
    if (wid < BPC) {
        const int b = wid;
        const float* tr = tape + (b * NSLOT + lane) * 65;
        const float* wk = xw + b * DIMN + dbase;
        float s = 0.f;
#pragma unroll
        for (int d = 0; d < DCH; ++d) s += tr[d] * wk[d];
        uint32_t off = a_xc + (unsigned)(rk * 264 + b * 66 + 2 * lane) * 4u;
#pragma unroll
        for (int p = 0; p < RANKS; ++p) sts_cluster_f32(mapa_rank(off, p), s);
        __syncwarp();
        if (lane == 0) {
#pragma unroll
            for (int p = 0; p < RANKS; ++p) mbar_arrive_cl(mapa_rank(a_mbC, p));
        }
    }
    mbar_wait_parity_cl(a_mbC, 0u);
    if (wid < BPC) {
        const int b = wid;
        float s = 0.f;
#pragma unroll
        for (int r = 0; r < RANKS; ++r) s += xc[r * 264 + b * 66 + 2 * lane];
        coefA[b * 32 + lane] = entmax_coef(s * invsd, sortb + b * 32, lane);
    }

    // ---- prologue W_h GEMV on h(-1)=work0 -> part_h ----
    {
        const float4* X4 = reinterpret_cast<const float4*>(xw);
        if (wid < 8) {
            const float4* W4 = reinterpret_cast<const float4*>(wsm)
                               + (size_t)(wid * 16) * 64 + lane;
            float a0=0,a1=0,a2=0,a3=0,b0a=0,b1a=0,b2a=0,b3a=0;
#pragma unroll
            for (int i = 0; i < 16; ++i) {
                int k4 = wid * 16 + i;
                float4 w0 = W4[i * 64];
                float4 w1 = W4[i * 64 + 32];
                float4 x0 = X4[0*128 + k4], x1 = X4[1*128 + k4];
                float4 x2 = X4[2*128 + k4], x3 = X4[3*128 + k4];
                a0 += w0.x*x0.x + w0.y*x0.y + w0.z*x0.z + w0.w*x0.w;
                a1 += w0.x*x1.x + w0.y*x1.y + w0.z*x1.z + w0.w*x1.w;
                a2 += w0.x*x2.x + w0.y*x2.y + w0.z*x2.z + w0.w*x2.w;
                a3 += w0.x*x3.x + w0.y*x3.y + w0.z*x3.z + w0.w*x3.w;
                b0a += w1.x*x0.x + w1.y*x0.y + w1.z*x0.z + w1.w*x0.w;
                b1a += w1.x*x1.x + w1.y*x1.y + w1.z*x1.z + w1.w*x1.w;
                b2a += w1.x*x2.x + w1.y*x2.y + w1.z*x2.z + w1.w*x2.w;
                b3a += w1.x*x3.x + w1.y*x3.y + w1.z*x3.z + w1.w*x3.w;
            }
            float* ph = part_h + wid * 256 + lane;
            ph[0]=a0; ph[64]=a1; ph[128]=a2; ph[192]=a3;
            ph[32]=b0a; ph[96]=b1a; ph[160]=b2a; ph[224]=b3a;
        }
    }

    // initial pre prefetch (t=0)
    float pre_reg = 0.f;
    if (tid < 256) {
        const int b = tid >> 6, d = tid & 63;
        pre_reg = __ldcs(&g_pre[((size_t)(b0 + b) * TSTEPS) * DIMN + dbase + d]);
    }
    __syncthreads();

    for (int t = 0; t < TSTEPS; ++t) {
        const int ni = (t & 1) ^ 1;
        const int cp = (t + 1) & 1;   // C exchange parity this step
        const int bp = t & 1;         // B exchange parity

        // ---- finish h(t): warps 0-7 (b=tid>>6, d=tid&63); per-warp arrive B ----
        if (tid < 256) {
            const int b = tid >> 6, d = tid & 63;
            float acc = pre_reg;
#pragma unroll
            for (int s = 0; s < 8; ++s) acc += part_h[s * 256 + b * 64 + d];
            const float* tr = tape + b * NSLOT * 65 + d;
            const float* cf = coefA + b * 32;
#pragma unroll 8
            for (int n = 0; n < NSLOT; ++n) acc += cf[n] * tr[n * 65];
            float h = tanhf(acc);
            __stcs(&out_hseq[((size_t)(b0 + b) * TSTEPS + t) * DIMN + dbase + d], h);
            uint32_t off = a_xw + (unsigned)(ni * 2048 + b * DIMN + dbase + d) * 4u;
#pragma unroll
            for (int p = 0; p < RANKS; ++p) sts_cluster_f32(mapa_rank(off, p), h);
            // prefetch pre(t+1) — lands during GEMV/scores/entmax
            int tn = (t + 1 < TSTEPS) ? t + 1 : t;
            pre_reg = __ldcs(&g_pre[((size_t)(b0 + b) * TSTEPS + tn) * DIMN + dbase + d]);
            __syncwarp();
            if (lane == 0) {
#pragma unroll
                for (int p = 0; p < RANKS; ++p) mbar_arrive_cl(mapa_rank(a_mbB, p));
            }
        }
        mbar_wait_parity_cl(a_mbB, (uint32_t)bp);

        // ---- fused dual GEMV on h(t): warps 0-7 W_h (smem), 8-15 W_w (gmem) ----
        {
            const float4* X4 = reinterpret_cast<const float4*>(xw + ni * 2048);
            float a0=0,a1=0,a2=0,a3=0,c0a=0,c1a=0,c2a=0,c3a=0;
            if (wid < 8) {
                const float4* W4 = reinterpret_cast<const float4*>(wsm)
                                   + (size_t)(wid * 16) * 64 + lane;
#pragma unroll
                for (int i = 0; i < 16; ++i) {
                    int k4 = wid * 16 + i;
                    float4 w0 = W4[i * 64];
                    float4 w1 = W4[i * 64 + 32];
                    float4 x0 = X4[0*128 + k4], x1 = X4[1*128 + k4];
                    float4 x2 = X4[2*128 + k4], x3 = X4[3*128 + k4];
                    a0 += w0.x*x0.x + w0.y*x0.y + w0.z*x0.z + w0.w*x0.w;
                    a1 += w0.x*x1.x + w0.y*x1.y + w0.z*x1.z + w0.w*x1.w;
                    a2 += w0.x*x2.x + w0.y*x2.y + w0.z*x2.z + w0.w*x2.w;
                    a3 += w0.x*x3.x + w0.y*x3.y + w0.z*x3.z + w0.w*x3.w;
                    c0a += w1.x*x0.x + w1.y*x0.y + w1.z*x0.z + w1.w*x0.w;
                    c1a += w1.x*x1.x + w1.y*x1.y + w1.z*x1.z + w1.w*x1.w;
                    c2a += w1.x*x2.x + w1.y*x2.y + w1.z*x2.z + w1.w*x2.w;
                    c3a += w1.x*x3.x + w1.y*x3.y + w1.z*x3.z + w1.w*x3.w;
                }
                float* ph = part_h + wid * 256 + lane;
                ph[0]=a0; ph[64]=a1; ph[128]=a2; ph[192]=a3;
                ph[32]=c0a; ph[96]=c1a; ph[160]=c2a; ph[224]=c3a;
            } else {
                const int w = wid - 8;
                const float4* W4 = reinterpret_cast<const float4*>(g_WwP)
                                   + (size_t)(w * 16) * DIMN + dbase + lane;
#pragma unroll
                for (int i = 0; i < 16; ++i) {
                    int k4 = w * 16 + i;
                    float4 w0 = __ldg(W4 + (size_t)i * DIMN);
                    float4 w1 = __ldg(W4 + (size_t)i * DIMN + 32);
                    float4 x0 = X4[0*128 + k4], x1 = X4[1*128 + k4];
                    float4 x2 = X4[2*128 + k4], x3 = X4[3*128 + k4];
                    a0 += w0.x*x0.x + w0.y*x0.y + w0.z*x0.z + w0.w*x0.w;
                    a1 += w0.x*x1.x + w0.y*x1.y + w0.z*x1.z + w0.w*x1.w;
                    a2 += w0.x*x2.x + w0.y*x2.y + w0.z*x2.z + w0.w*x2.w;
                    a3 += w0.x*x3.x + w0.y*x3.y + w0.z*x3.z + w0.w*x3.w;
                    c0a += w1.x*x0.x + w1.y*x0.y + w1.z*x0.z + w1.w*x0.w;
                    c1a += w1.x*x1.x + w1.y*x1.y + w1.z*x1.z + w1.w*x1.w;
                    c2a += w1.x*x2.x + w1.y*x2.y + w1.z*x2.z + w1.w*x2.w;
                    c3a += w1.x*x3.x + w1.y*x3.y + w1.z*x3.z + w1.w*x3.w;
                }
                float* pw = part_w + w * 256 + lane;
                pw[0]=a0; pw[64]=a1; pw[128]=a2; pw[192]=a3;
                pw[32]=c0a; pw[96]=c1a; pw[160]=c2a; pw[224]=c3a;
            }
        }
        __syncthreads();

        // ---- scores (warps 0-3): reduce wvec in-warp + sA,sB,sC + push ----
        if (wid < BPC) {
            const int b = wid;
            float wv0 = 0.f, wv1 = 0.f;
#pragma unroll
            for (int s = 0; s < 8; ++s) {
                wv0 += part_w[s * 256 + b * 64 + lane];
                wv1 += part_w[s * 256 + b * 64 + 32 + lane];
            }
            wvec[b * 64 + lane]      = wv0;
            wvec[b * 64 + 32 + lane] = wv1;
            __syncwarp();

            const float* tr = tape + (b * NSLOT + lane) * 65;
            const float* wv = wvec + b * 64;
            const float* hh = xw + ni * 2048 + b * DIMN + dbase;
            float sA = 0.f, sB = 0.f;
#pragma unroll
            for (int d = 0; d < DCH; ++d) {
                float tv = tr[d];
                sA += tv * wv[d];
                sB += tv * hh[d];
            }
            // sC from registers
            float v = wv0 * hh[lane] + wv1 * hh[32 + lane];
#pragma unroll
            for (int o = 16; o > 0; o >>= 1) v += __shfl_xor_sync(0xffffffffu, v, o);

            uint32_t off = a_xc + (unsigned)(cp * 2112 + rk * 264 + b * 66 + 2 * lane) * 4u;
#pragma unroll
            for (int p = 0; p < RANKS; ++p) sts_cluster_f32x2(mapa_rank(off, p), sA, sB);
            if (lane == 0) {
                uint32_t offc = a_xc + (unsigned)(cp * 2112 + rk * 264 + b * 66 + 64) * 4u;
#pragma unroll
                for (int p = 0; p < RANKS; ++p) sts_cluster_f32(mapa_rank(offc, p), v);
            }
            __syncwarp();
            if (lane == 0) {
#pragma unroll
                for (int p = 0; p < RANKS; ++p) mbar_arrive_cl(mapa_rank(a_mbC, p));
            }
        }
        mbar_wait_parity_cl(a_mbC, (uint32_t)cp);

        // ---- f1: reduce + beta = entmax(sA) (warps 0-3) ----
        float sBr = 0.f, sCr = 0.f, betar = 0.f;
        if (wid < BPC) {
            const int b = wid;
            const float* base = xc + cp * 2112 + b * 66;
            float sA = 0.f;
#pragma unroll
            for (int r = 0; r < RANKS; ++r) {
                float2 pr = *reinterpret_cast<const float2*>(base + r * 264 + 2 * lane);
                sA  += pr.x;
                sBr += pr.y;
                sCr += base[r * 264 + 64];
            }
            betar = entmax_coef(sA * invsd, sortb + b * 32, lane);
            coefB[b * 32 + lane] = betar;
        }
        __syncthreads();

        // ---- f2: alpha(t+1) (warps 0-3) || tape update (warps 4-11) ----
        if (wid < BPC) {
            const int b = wid;
            float rn = ((1.f - betar) * sBr + betar * sCr) * invsd;
            coefA[b * 32 + lane] = entmax_coef(rn, sortb + b * 32, lane);
        } else if (wid < 12) {
            const int idx = wid - 4;
            const int b  = idx >> 1;
            const int n0 = (idx & 1) * 16;
            const float* wv = wvec + b * 64;
            const float* cf = coefB + b * 32 + n0;
            float* tb = tape + (b * NSLOT + n0) * 65;
#pragma unroll
            for (int n = 0; n < 16; ++n) {
                float bt  = cf[n];
                float omb = 1.f - bt;
                float* row = tb + n * 65;
                row[lane]      = row[lane]      * omb + bt * wv[lane];
                row[lane + 32] = row[lane + 32] * omb + bt * wv[lane + 32];
            }
        }
        __syncthreads();
    }

    // ---- final outputs ----
    for (int i = tid; i < BPC * NSLOT * DCH; i += NTHR) {
        int b = i >> 11;
        int n = (i >> 6) & 31;
        int d = i & 63;
        out_tape[((size_t)(b0 + b) * NSLOT + n) * DIMN + dbase + d] =
            tape[(b * NSLOT + n) * 65 + d];
    }
    if (tid < 256) {
        const int b = tid >> 6, d = tid & 63;
        // h(2047): ni at t=2047 is 0
        out_hlast[(size_t)(b0 + b) * DIMN + dbase + d] = xw[b * DIMN + dbase + d];
    }
    cluster_sync_();
}

// ---------------- launch ----------------
extern "C" void kernel_launch(void* const* d_in, const int* in_sizes, int n_in,
                              void* d_out, int out_size) {
    const float* x     = (const float*)d_in[0];
    const float* tape0 = (const float*)d_in[1];
    const float* work0 = (const float*)d_in[2];
    const float* Wh    = (const float*)d_in[3];
    const float* Wx    = (const float*)d_in[4];
    const float* bh    = (const float*)d_in[5];
    const float* Ww    = (const float*)d_in[6];

    float* out       = (float*)d_out;
    float* out_hseq  = out;
    float* out_tape  = out + (size_t)BATCH * TSTEPS * DIMN;
    float* out_hlast = out_tape + (size_t)BATCH * NSLOT * DIMN;

    pack_weights<<<(DIMN * DIMN + 511) / 512, 512>>>(Wh, Ww);

    dim3 ggrid(DIMN / 64, (BATCH * TSTEPS) / 128);
    gemm_pre<<<ggrid, 256>>>(x, Wx, bh);

    const int smem_bytes = SM_FLOATS * 4 + 16;   // ~216.6 KB
    cudaFuncSetAttribute(recur8, cudaFuncAttributeMaxDynamicSharedMemorySize, smem_bytes);
    recur8<<<(BATCH / BPC) * RANKS, NTHR, smem_bytes>>>(
        tape0, work0, out_hseq, out_tape, out_hlast);
}

// round 9
// speedup vs baseline: 1.0450x; 1.0450x over previous
#include <cuda_runtime.h>
#include <cuda_bf16.h>
#include <cstddef>
#include <cstdint>

#define DIMN   512
#define NSLOT  32
#define BATCH  32
#define TSTEPS 2048
#define RANKS  8      // cluster size = d-chunks
#define BPC    4      // batches per CTA
#define DCH    64     // d columns per CTA
#define NTHR   512

// ---------------- scratch ----------------
__device__ float g_pre[(size_t)BATCH * TSTEPS * DIMN];
__device__ float g_WhP[DIMN * DIMN];   // packed: float4 idx = k4*DIMN + d
__device__ float g_WwP[DIMN * DIMN];

// ---------------- PTX helpers ----------------
__device__ __forceinline__ uint32_t smem_u32(const void* p) {
    uint32_t a;
    asm("{ .reg .u64 t; cvta.to.shared.u64 t, %1; cvt.u32.u64 %0, t; }"
        : "=r"(a) : "l"(p));
    return a;
}
__device__ __forceinline__ uint32_t mapa_rank(uint32_t laddr, uint32_t rank) {
    uint32_t r;
    asm("mapa.shared::cluster.u32 %0, %1, %2;" : "=r"(r) : "r"(laddr), "r"(rank));
    return r;
}
__device__ __forceinline__ void sts_cluster_f32(uint32_t addr, float v) {
    asm volatile("st.shared::cluster.f32 [%0], %1;" :: "r"(addr), "f"(v) : "memory");
}
__device__ __forceinline__ void sts_cluster_f32x2(uint32_t addr, float a, float b) {
    asm volatile("st.shared::cluster.v2.f32 [%0], {%1, %2};"
                 :: "r"(addr), "f"(a), "f"(b) : "memory");
}
__device__ __forceinline__ void mbar_init(uint32_t addr, uint32_t cnt) {
    asm volatile("mbarrier.init.shared.b64 [%0], %1;" :: "r"(addr), "r"(cnt) : "memory");
}
__device__ __forceinline__ void mbar_arrive_cl(uint32_t remAddr) {
    asm volatile("mbarrier.arrive.release.cluster.shared::cluster.b64 _, [%0];"
                 :: "r"(remAddr) : "memory");
}
__device__ __forceinline__ void mbar_wait_parity_cl(uint32_t addr, uint32_t parity) {
    asm volatile(
        "{\n\t"
        ".reg .pred P;\n\t"
        "LAB_WAIT_%=:\n\t"
        "mbarrier.try_wait.parity.acquire.cluster.shared::cta.b64 P, [%0], %1, 0x989680;\n\t"
        "@P bra.uni LAB_DONE_%=;\n\t"
        "bra.uni LAB_WAIT_%=;\n\t"
        "LAB_DONE_%=:\n\t"
        "}"
        :: "r"(addr), "r"(parity) : "memory");
}
__device__ __forceinline__ void cluster_sync_() {
    asm volatile("barrier.cluster.arrive.aligned;\n\tbarrier.cluster.wait.aligned;" ::: "memory");
}

// ---------------- dummy (shifts ncu -s 5 capture onto recur) ----------------
__global__ void dummy_k() {}

// ---------------- weight packing ----------------
__global__ void pack_weights(const float* __restrict__ Wh,
                             const float* __restrict__ Ww) {
    int idx = blockIdx.x * blockDim.x + threadIdx.x;
    if (idx >= DIMN * DIMN) return;
    int d = idx / DIMN;
    int k = idx % DIMN;
    int dst = ((k >> 2) * DIMN + d) * 4 + (k & 3);
    g_WhP[dst] = Wh[idx];
    g_WwP[dst] = Ww[idx];
}

// ---------------- pre-GEMM ----------------
__global__ __launch_bounds__(256) void gemm_pre(
    const float* __restrict__ X,
    const float* __restrict__ W,
    const float* __restrict__ bias)
{
    __shared__ float As[8][128];
    __shared__ float Bs[8][64];

    const int tid = threadIdx.x;
    const int m0 = blockIdx.y * 128;
    const int n0 = blockIdx.x * 64;
    const int trow = tid >> 4;
    const int tcol = tid & 15;

    float acc[8][4];
#pragma unroll
    for (int i = 0; i < 8; ++i)
#pragma unroll
        for (int j = 0; j < 4; ++j) acc[i][j] = 0.f;

    const int a_m  = tid >> 1;
    const int a_k4 = (tid & 1) * 4;

    for (int k0 = 0; k0 < DIMN; k0 += 8) {
        float4 av = *reinterpret_cast<const float4*>(
            X + (size_t)(m0 + a_m) * DIMN + k0 + a_k4);
        As[a_k4 + 0][a_m] = av.x;
        As[a_k4 + 1][a_m] = av.y;
        As[a_k4 + 2][a_m] = av.z;
        As[a_k4 + 3][a_m] = av.w;
        if (tid < 128) {
            int bn  = tid >> 1;
            int bk4 = (tid & 1) * 4;
            float4 bv = *reinterpret_cast<const float4*>(
                W + (size_t)(n0 + bn) * DIMN + k0 + bk4);
            Bs[bk4 + 0][bn] = bv.x;
            Bs[bk4 + 1][bn] = bv.y;
            Bs[bk4 + 2][bn] = bv.z;
            Bs[bk4 + 3][bn] = bv.w;
        }
        __syncthreads();
#pragma unroll
        for (int kk = 0; kk < 8; ++kk) {
            float4 ra0 = *reinterpret_cast<const float4*>(&As[kk][trow * 8]);
            float4 ra1 = *reinterpret_cast<const float4*>(&As[kk][trow * 8 + 4]);
            float4 rb  = *reinterpret_cast<const float4*>(&Bs[kk][tcol * 4]);
            float ra[8] = {ra0.x, ra0.y, ra0.z, ra0.w, ra1.x, ra1.y, ra1.z, ra1.w};
            float rbv[4] = {rb.x, rb.y, rb.z, rb.w};
#pragma unroll
            for (int i = 0; i < 8; ++i)
#pragma unroll
                for (int j = 0; j < 4; ++j) acc[i][j] += ra[i] * rbv[j];
        }
        __syncthreads();
    }

    float4 bj = *reinterpret_cast<const float4*>(bias + n0 + tcol * 4);
#pragma unroll
    for (int i = 0; i < 8; ++i) {
        float4 v;
        v.x = acc[i][0] + bj.x;
        v.y = acc[i][1] + bj.y;
        v.z = acc[i][2] + bj.z;
        v.w = acc[i][3] + bj.w;
        *reinterpret_cast<float4*>(
            &g_pre[(size_t)(m0 + trow * 8 + i) * DIMN + n0 + tcol * 4]) = v;
    }
}

// ---------------- exact entmax-1.5 (warp-collective, lane = slot) ----------------
__device__ __forceinline__ float entmax_coef(float raw, float* __restrict__ sb, int lane) {
    const unsigned FULL = 0xffffffffu;
    float z = raw * 0.5f;
    float m = z;
#pragma unroll
    for (int o = 16; o > 0; o >>= 1) m = fmaxf(m, __shfl_xor_sync(FULL, m, o));
    z -= m;

    int rank = 0;
#pragma unroll
    for (int j = 0; j < 32; ++j) {
        float zj = __shfl_sync(FULL, z, j);
        rank += (zj > z) || (zj == z && j < lane);
    }
    sb[rank] = z;
    __syncwarp();
    float zs = sb[lane];

    float cs = zs, cq = zs * zs;
#pragma unroll
    for (int o = 1; o < 32; o <<= 1) {
        float a  = __shfl_up_sync(FULL, cs, o);
        float bq = __shfl_up_sync(FULL, cq, o);
        if (lane >= o) { cs += a; cq += bq; }
    }
    float k    = (float)(lane + 1);
    float mean = cs / k;
    float msq  = cq / k;
    float ss   = k * (msq - mean * mean);
    float delta = fmaxf((1.f - ss) / k, 0.f);
    float tau   = mean - sqrtf(delta);

    unsigned sup = __ballot_sync(FULL, tau <= zs);
    int kstar = __popc(sup) - 1;
    float tau_star = __shfl_sync(FULL, tau, kstar);
    float p = fmaxf(z - tau_star, 0.f);
    return p * p;
}

// ---------------- weight refill into registers (16 float4 per warp) ----------
__device__ __forceinline__ void load_w(float4* wreg, const float* __restrict__ Wp,
                                       int wid, int lane, int dbase) {
    const float4* W4 = reinterpret_cast<const float4*>(Wp)
                       + (size_t)(wid * 8) * DIMN + dbase + lane;
#pragma unroll
    for (int i = 0; i < 8; ++i) {
        wreg[i]     = __ldg(W4 + (size_t)i * DIMN);
        wreg[8 + i] = __ldg(W4 + (size_t)i * DIMN + 32);
    }
}

// ---------------- GEMV partials from register weights ----------------
// 16 warps = 16 k-segments of 32; lane covers d=lane and d=lane+32; 4 batches
__device__ __forceinline__ void gemv16_reg(const float4* __restrict__ wreg,
                                           const float4* __restrict__ xw4, // [4][128]
                                           float* __restrict__ part,
                                           int wid, int lane) {
    float a0 = 0.f, a1 = 0.f, a2 = 0.f, a3 = 0.f;
    float b0 = 0.f, b1 = 0.f, b2 = 0.f, b3 = 0.f;
#pragma unroll
    for (int i = 0; i < 8; ++i) {
        float4 w0 = wreg[i];
        float4 w1 = wreg[8 + i];
        float4 k0 = xw4[0 * 128 + wid * 8 + i];
        float4 k1 = xw4[1 * 128 + wid * 8 + i];
        float4 k2 = xw4[2 * 128 + wid * 8 + i];
        float4 k3 = xw4[3 * 128 + wid * 8 + i];
        a0 += w0.x * k0.x + w0.y * k0.y + w0.z * k0.z + w0.w * k0.w;
        a1 += w0.x * k1.x + w0.y * k1.y + w0.z * k1.z + w0.w * k1.w;
        a2 += w0.x * k2.x + w0.y * k2.y + w0.z * k2.z + w0.w * k2.w;
        a3 += w0.x * k3.x + w0.y * k3.y + w0.z * k3.z + w0.w * k3.w;
        b0 += w1.x * k0.x + w1.y * k0.y + w1.z * k0.z + w1.w * k0.w;
        b1 += w1.x * k1.x + w1.y * k1.y + w1.z * k1.z + w1.w * k1.w;
        b2 += w1.x * k2.x + w1.y * k2.y + w1.z * k2.z + w1.w * k2.w;
        b3 += w1.x * k3.x + w1.y * k3.y + w1.z * k3.z + w1.w * k3.w;
    }
    float* pp = part + wid * 256 + lane;
    pp[0]   = a0;  pp[64]  = a1;  pp[128] = a2;  pp[192] = a3;
    pp[32]  = b0;  pp[96]  = b1;  pp[160] = b2;  pp[224] = b3;
}

// ---------------- SMEM float offsets ----------------
#define SM_PART   0       // [16][4][64]          4096
#define SM_XW     4096    // [2][4][512]          4096
#define SM_WVEC   8192    // [4][64]              256
#define SM_COEFA  8448    // [4][32]              128
#define SM_COEFB  8576    // [4][32]              128
#define SM_SORT   8704    // [4][32]              128
#define SM_TAPE   8832    // [4][32][65]          8320
#define SM_XC     17152   // [2][8][4][130]       8320
#define SM_MBARB  25472   // u64
#define SM_MBARC  25474   // u64
#define SM_FLOATS 25476

// ---------------- persistent recurrence ----------------
__global__ void __launch_bounds__(NTHR, 1) __cluster_dims__(RANKS, 1, 1)
recur9(const float* __restrict__ tape0,
       const float* __restrict__ work0,
       float* __restrict__ out_hseq,
       float* __restrict__ out_tape,
       float* __restrict__ out_hlast)
{
    extern __shared__ float sm[];
    float* part_h = sm + SM_PART;          // reused for both GEMVs? no: see below
    float* xw     = sm + SM_XW;
    float* wvec   = sm + SM_WVEC;
    float* coefA  = sm + SM_COEFA;
    float* coefB  = sm + SM_COEFB;
    float* sortb  = sm + SM_SORT;
    float* tape   = sm + SM_TAPE;
    float* xc     = sm + SM_XC;
    float* part   = part_h;                // single part buffer (phases are serialized)

    const int tid  = threadIdx.x;
    const int lane = tid & 31;
    const int wid  = tid >> 5;
    const int rk   = blockIdx.x & (RANKS - 1);
    const int bg   = blockIdx.x >> 3;
    const int b0   = bg * BPC;
    const int dbase = rk * DCH;

    const uint32_t sbase = smem_u32(sm);
    const uint32_t a_xw  = sbase + SM_XW * 4u;
    const uint32_t a_xc  = sbase + SM_XC * 4u;
    const uint32_t a_mbB = sbase + SM_MBARB * 4u;
    const uint32_t a_mbC = sbase + SM_MBARC * 4u;

    if (tid == 0) {
        mbar_init(a_mbB, RANKS);
        mbar_init(a_mbC, RANKS);
    }

    // ---- prologue loads ----
    for (int i = tid; i < BPC * NSLOT * DCH; i += NTHR) {
        int b = i >> 11;
        int n = (i >> 6) & 31;
        int d = i & 63;
        tape[(b * NSLOT + n) * 65 + d] =
            tape0[((size_t)(b0 + b) * NSLOT + n) * DIMN + dbase + d];
    }
    for (int i = tid; i < BPC * DIMN; i += NTHR) {
        int b = i >> 9;
        int k = i & 511;
        xw[b * DIMN + k] = work0[(size_t)(b0 + b) * DIMN + k];
    }
    __syncthreads();
    cluster_sync_();

    const float invsd = 0.044194173824159216f;  // 1/sqrt(512)

    // weight registers: start holding W_h slice
    float4 wreg[16];
    load_w(wreg, g_WhP, wid, lane, dbase);

    // ---- initial read-scores exchange (parity 0) ----
    if (wid < BPC) {
        const int b = wid;
        const float* tr = tape + (b * NSLOT + lane) * 65;
        const float* wk = xw + b * DIMN + dbase;
        float s = 0.f;
#pragma unroll
        for (int d = 0; d < DCH; ++d) s += tr[d] * wk[d];
        uint32_t off = a_xc + (unsigned)(rk * 264 + b * 66 + 2 * lane) * 4u;
#pragma unroll
        for (int p = 0; p < RANKS; ++p) sts_cluster_f32(mapa_rank(off, p), s);
    }
    __syncthreads();
    if (tid == 0) {
#pragma unroll
        for (int p = 0; p < RANKS; ++p) mbar_arrive_cl(mapa_rank(a_mbC, p));
    }
    mbar_wait_parity_cl(a_mbC, 0u);
    if (wid < BPC) {
        const int b = wid;
        float s = 0.f;
#pragma unroll
        for (int r = 0; r < RANKS; ++r) s += xc[r * 264 + b * 66 + 2 * lane];
        coefA[b * 32 + lane] = entmax_coef(s * invsd, sortb + b * 32, lane);
    }

    // initial pre prefetch (t=0)
    float pre_reg = 0.f;
    if (tid < 256) {
        const int b = tid >> 6, d = tid & 63;
        pre_reg = __ldcs(&g_pre[((size_t)(b0 + b) * TSTEPS) * DIMN + dbase + d]);
    }
    __syncthreads();

    for (int t = 0; t < TSTEPS; ++t) {
        const int oldi = t & 1;
        const int ni   = oldi ^ 1;
        const int cp   = (t + 1) & 1;   // C exchange parity
        const int bp   = t & 1;         // B exchange parity

        // ---- phase A: W_h GEMV partials from registers; refill wreg <- W_w ----
        gemv16_reg(wreg, reinterpret_cast<const float4*>(xw + oldi * 2048),
                   part, wid, lane);
        load_w(wreg, g_WwP, wid, lane, dbase);   // latency covered by finish-h + exchange
        __syncthreads();

        // ---- finish h(t): tid<256 (b=tid>>6, d=tid&63); prefetch pre(t+1) ----
        if (tid < 256) {
            const int b = tid >> 6, d = tid & 63;
            float acc = pre_reg;
#pragma unroll
            for (int s = 0; s < 16; ++s) acc += part[s * 256 + b * 64 + d];
            const float* tr = tape + b * NSLOT * 65 + d;
            const float* cf = coefA + b * 32;
#pragma unroll 8
            for (int n = 0; n < NSLOT; ++n) acc += cf[n] * tr[n * 65];
            float h = tanhf(acc);
            __stcs(&out_hseq[((size_t)(b0 + b) * TSTEPS + t) * DIMN + dbase + d], h);
            uint32_t off = a_xw + (unsigned)(ni * 2048 + b * DIMN + dbase + d) * 4u;
#pragma unroll
            for (int p = 0; p < RANKS; ++p) sts_cluster_f32(mapa_rank(off, p), h);
            int tn = (t + 1 < TSTEPS) ? t + 1 : t;
            pre_reg = __ldcs(&g_pre[((size_t)(b0 + b) * TSTEPS + tn) * DIMN + dbase + d]);
        }
        __syncthreads();
        if (tid == 0) {
#pragma unroll
            for (int p = 0; p < RANKS; ++p) mbar_arrive_cl(mapa_rank(a_mbB, p));
        }
        mbar_wait_parity_cl(a_mbB, (uint32_t)bp);

        // ---- phase B: W_w GEMV partials from registers; refill wreg <- W_h ----
        gemv16_reg(wreg, reinterpret_cast<const float4*>(xw + ni * 2048),
                   part, wid, lane);
        load_w(wreg, g_WhP, wid, lane, dbase);   // latency covered by scores + exchange C
        __syncthreads();

        // ---- reduce wvec (tid<256) ----
        if (tid < 256) {
            const int b = tid >> 6, d = tid & 63;
            float acc = 0.f;
#pragma unroll
            for (int s = 0; s < 16; ++s) acc += part[s * 256 + b * 64 + d];
            wvec[b * 64 + d] = acc;
        }
        __syncthreads();

        // ---- scores: warps 0-3 (sA,sB) 64-d dots; warps 4-7 (sC) ----
        if (wid < BPC) {
            const int b = wid;
            const float* tr = tape + (b * NSLOT + lane) * 65;
            const float* wv = wvec + b * 64;
            const float* hh = xw + ni * 2048 + b * DIMN + dbase;
            float sA = 0.f, sB = 0.f;
#pragma unroll
            for (int d = 0; d < DCH; ++d) {
                float tv = tr[d];
                sA += tv * wv[d];
                sB += tv * hh[d];
            }
            uint32_t off = a_xc + (unsigned)(cp * 2112 + rk * 264 + b * 66 + 2 * lane) * 4u;
#pragma unroll
            for (int p = 0; p < RANKS; ++p) sts_cluster_f32x2(mapa_rank(off, p), sA, sB);
        } else if (wid < 8) {
            const int b = wid - 4;
            const float* hh = xw + ni * 2048 + b * DIMN + dbase;
            float v = wvec[b * 64 + lane] * hh[lane]
                    + wvec[b * 64 + 32 + lane] * hh[32 + lane];
#pragma unroll
            for (int o = 16; o > 0; o >>= 1) v += __shfl_xor_sync(0xffffffffu, v, o);
            if (lane == 0) {
                uint32_t off = a_xc + (unsigned)(cp * 2112 + rk * 264 + b * 66 + 64) * 4u;
#pragma unroll
                for (int p = 0; p < RANKS; ++p) sts_cluster_f32(mapa_rank(off, p), v);
            }
        }
        __syncthreads();
        if (tid == 0) {
#pragma unroll
            for (int p = 0; p < RANKS; ++p) mbar_arrive_cl(mapa_rank(a_mbC, p));
        }
        mbar_wait_parity_cl(a_mbC, (uint32_t)cp);

        // ---- D: reduce; beta = entmax(sA); alpha(t+1) via score recurrence ----
        if (wid < BPC) {
            const int b = wid;
            const float* base = xc + cp * 2112 + b * 66;
            float sA = 0.f, sB = 0.f, sC = 0.f;
#pragma unroll
            for (int r = 0; r < RANKS; ++r) {
                float2 pr = *reinterpret_cast<const float2*>(base + r * 264 + 2 * lane);
                sA += pr.x;
                sB += pr.y;
                sC += base[r * 264 + 64];
            }
            float beta = entmax_coef(sA * invsd, sortb + b * 32, lane);
            coefB[b * 32 + lane] = beta;
            float rnext = ((1.f - beta) * sB + beta * sC) * invsd;
            coefA[b * 32 + lane] = entmax_coef(rnext, sortb + b * 32, lane);
        }
        __syncthreads();

        // ---- E: tape convex update (16 warps: b, 8-slot group) ----
        {
            const int b = wid & 3;
            const int n0 = (wid >> 2) * 8;
            const float* wv = wvec + b * 64;
            const float* cf = coefB + b * 32 + n0;
            float* tb = tape + (b * NSLOT + n0) * 65;
#pragma unroll
            for (int n = 0; n < 8; ++n) {
                float bt = cf[n];
                float omb = 1.f - bt;
                float* row = tb + n * 65;
                row[lane]      = row[lane]      * omb + bt * wv[lane];
                row[lane + 32] = row[lane + 32] * omb + bt * wv[lane + 32];
            }
        }
        __syncthreads();
    }

    // ---- final outputs ----
    for (int i = tid; i < BPC * NSLOT * DCH; i += NTHR) {
        int b = i >> 11;
        int n = (i >> 6) & 31;
        int d = i & 63;
        out_tape[((size_t)(b0 + b) * NSLOT + n) * DIMN + dbase + d] =
            tape[(b * NSLOT + n) * 65 + d];
    }
    if (tid < 256) {
        const int b = tid >> 6, d = tid & 63;
        // h(2047): ni at t=2047 is 0
        out_hlast[(size_t)(b0 + b) * DIMN + dbase + d] = xw[b * DIMN + dbase + d];
    }
    cluster_sync_();
}

// ---------------- launch ----------------
extern "C" void kernel_launch(void* const* d_in, const int* in_sizes, int n_in,
                              void* d_out, int out_size) {
    const float* x     = (const float*)d_in[0];
    const float* tape0 = (const float*)d_in[1];
    const float* work0 = (const float*)d_in[2];
    const float* Wh    = (const float*)d_in[3];
    const float* Wx    = (const float*)d_in[4];
    const float* bh    = (const float*)d_in[5];
    const float* Ww    = (const float*)d_in[6];

    float* out       = (float*)d_out;
    float* out_hseq  = out;
    float* out_tape  = out + (size_t)BATCH * TSTEPS * DIMN;
    float* out_hlast = out_tape + (size_t)BATCH * NSLOT * DIMN;

    dummy_k<<<1, 32>>>();   // shifts ncu -s 5 capture onto recur9

    pack_weights<<<(DIMN * DIMN + 511) / 512, 512>>>(Wh, Ww);

    dim3 ggrid(DIMN / 64, (BATCH * TSTEPS) / 128);
    gemm_pre<<<ggrid, 256>>>(x, Wx, bh);

    const int smem_bytes = SM_FLOATS * 4 + 16;
    cudaFuncSetAttribute(recur9, cudaFuncAttributeMaxDynamicSharedMemorySize, smem_bytes);
    recur9<<<(BATCH / BPC) * RANKS, NTHR, smem_bytes>>>(
        tape0, work0, out_hseq, out_tape, out_hlast);
}

// round 10
// speedup vs baseline: 1.0464x; 1.0014x over previous
#include <cuda_runtime.h>
#include <cuda_bf16.h>
#include <cstddef>
#include <cstdint>

#define DIMN   512
#define NSLOT  32
#define BATCH  32
#define TSTEPS 2048
#define RANKS  8      // cluster size = d-chunks
#define BPC    4      // batches per CTA
#define DCH    64     // d columns per CTA
#define NTHR   512

// ---------------- scratch ----------------
__device__ float g_pre[(size_t)BATCH * TSTEPS * DIMN];
__device__ float g_WhP[DIMN * DIMN];   // packed: float4 idx = k4*DIMN + d
__device__ float g_WwP[DIMN * DIMN];

// ---------------- PTX helpers ----------------
__device__ __forceinline__ uint32_t smem_u32(const void* p) {
    uint32_t a;
    asm("{ .reg .u64 t; cvta.to.shared.u64 t, %1; cvt.u32.u64 %0, t; }"
        : "=r"(a) : "l"(p));
    return a;
}
__device__ __forceinline__ uint32_t mapa_rank(uint32_t laddr, uint32_t rank) {
    uint32_t r;
    asm("mapa.shared::cluster.u32 %0, %1, %2;" : "=r"(r) : "r"(laddr), "r"(rank));
    return r;
}
__device__ __forceinline__ void sts_cluster_f32(uint32_t addr, float v) {
    asm volatile("st.shared::cluster.f32 [%0], %1;" :: "r"(addr), "f"(v) : "memory");
}
__device__ __forceinline__ void sts_cluster_f32x2(uint32_t addr, float a, float b) {
    asm volatile("st.shared::cluster.v2.f32 [%0], {%1, %2};"
                 :: "r"(addr), "f"(a), "f"(b) : "memory");
}
__device__ __forceinline__ void mbar_init(uint32_t addr, uint32_t cnt) {
    asm volatile("mbarrier.init.shared.b64 [%0], %1;" :: "r"(addr), "r"(cnt) : "memory");
}
__device__ __forceinline__ void mbar_arrive_cl(uint32_t remAddr) {
    asm volatile("mbarrier.arrive.release.cluster.shared::cluster.b64 _, [%0];"
                 :: "r"(remAddr) : "memory");
}
__device__ __forceinline__ void mbar_wait_parity_cl(uint32_t addr, uint32_t parity) {
    asm volatile(
        "{\n\t"
        ".reg .pred P;\n\t"
        "LAB_WAIT_%=:\n\t"
        "mbarrier.try_wait.parity.acquire.cluster.shared::cta.b64 P, [%0], %1, 0x989680;\n\t"
        "@P bra.uni LAB_DONE_%=;\n\t"
        "bra.uni LAB_WAIT_%=;\n\t"
        "LAB_DONE_%=:\n\t"
        "}"
        :: "r"(addr), "r"(parity) : "memory");
}
__device__ __forceinline__ void cluster_sync_() {
    asm volatile("barrier.cluster.arrive.aligned;\n\tbarrier.cluster.wait.aligned;" ::: "memory");
}

// ---------------- dummy (shifts ncu -s 5 capture onto recur) ----------------
__global__ void dummy_k() {}

// ---------------- weight packing ----------------
__global__ void pack_weights(const float* __restrict__ Wh,
                             const float* __restrict__ Ww) {
    int idx = blockIdx.x * blockDim.x + threadIdx.x;
    if (idx >= DIMN * DIMN) return;
    int d = idx / DIMN;
    int k = idx % DIMN;
    int dst = ((k >> 2) * DIMN + d) * 4 + (k & 3);
    g_WhP[dst] = Wh[idx];
    g_WwP[dst] = Ww[idx];
}

// ---------------- pre-GEMM ----------------
__global__ __launch_bounds__(256) void gemm_pre(
    const float* __restrict__ X,
    const float* __restrict__ W,
    const float* __restrict__ bias)
{
    __shared__ float As[8][128];
    __shared__ float Bs[8][64];

    const int tid = threadIdx.x;
    const int m0 = blockIdx.y * 128;
    const int n0 = blockIdx.x * 64;
    const int trow = tid >> 4;
    const int tcol = tid & 15;

    float acc[8][4];
#pragma unroll
    for (int i = 0; i < 8; ++i)
#pragma unroll
        for (int j = 0; j < 4; ++j) acc[i][j] = 0.f;

    const int a_m  = tid >> 1;
    const int a_k4 = (tid & 1) * 4;

    for (int k0 = 0; k0 < DIMN; k0 += 8) {
        float4 av = *reinterpret_cast<const float4*>(
            X + (size_t)(m0 + a_m) * DIMN + k0 + a_k4);
        As[a_k4 + 0][a_m] = av.x;
        As[a_k4 + 1][a_m] = av.y;
        As[a_k4 + 2][a_m] = av.z;
        As[a_k4 + 3][a_m] = av.w;
        if (tid < 128) {
            int bn  = tid >> 1;
            int bk4 = (tid & 1) * 4;
            float4 bv = *reinterpret_cast<const float4*>(
                W + (size_t)(n0 + bn) * DIMN + k0 + bk4);
            Bs[bk4 + 0][bn] = bv.x;
            Bs[bk4 + 1][bn] = bv.y;
            Bs[bk4 + 2][bn] = bv.z;
            Bs[bk4 + 3][bn] = bv.w;
        }
        __syncthreads();
#pragma unroll
        for (int kk = 0; kk < 8; ++kk) {
            float4 ra0 = *reinterpret_cast<const float4*>(&As[kk][trow * 8]);
            float4 ra1 = *reinterpret_cast<const float4*>(&As[kk][trow * 8 + 4]);
            float4 rb  = *reinterpret_cast<const float4*>(&Bs[kk][tcol * 4]);
            float ra[8] = {ra0.x, ra0.y, ra0.z, ra0.w, ra1.x, ra1.y, ra1.z, ra1.w};
            float rbv[4] = {rb.x, rb.y, rb.z, rb.w};
#pragma unroll
            for (int i = 0; i < 8; ++i)
#pragma unroll
                for (int j = 0; j < 4; ++j) acc[i][j] += ra[i] * rbv[j];
        }
        __syncthreads();
    }

    float4 bj = *reinterpret_cast<const float4*>(bias + n0 + tcol * 4);
#pragma unroll
    for (int i = 0; i < 8; ++i) {
        float4 v;
        v.x = acc[i][0] + bj.x;
        v.y = acc[i][1] + bj.y;
        v.z = acc[i][2] + bj.z;
        v.w = acc[i][3] + bj.w;
        *reinterpret_cast<float4*>(
            &g_pre[(size_t)(m0 + trow * 8 + i) * DIMN + n0 + tcol * 4]) = v;
    }
}

// ---------------- exact entmax-1.5 (warp-collective, lane = slot) ----------------
__device__ __forceinline__ float entmax_coef(float raw, float* __restrict__ sb, int lane) {
    const unsigned FULL = 0xffffffffu;
    float z = raw * 0.5f;
    float m = z;
#pragma unroll
    for (int o = 16; o > 0; o >>= 1) m = fmaxf(m, __shfl_xor_sync(FULL, m, o));
    z -= m;

    int rank = 0;
#pragma unroll
    for (int j = 0; j < 32; ++j) {
        float zj = __shfl_sync(FULL, z, j);
        rank += (zj > z) || (zj == z && j < lane);
    }
    sb[rank] = z;
    __syncwarp();
    float zs = sb[lane];

    float cs = zs, cq = zs * zs;
#pragma unroll
    for (int o = 1; o < 32; o <<= 1) {
        float a  = __shfl_up_sync(FULL, cs, o);
        float bq = __shfl_up_sync(FULL, cq, o);
        if (lane >= o) { cs += a; cq += bq; }
    }
    float k    = (float)(lane + 1);
    float mean = cs / k;
    float msq  = cq / k;
    float ss   = k * (msq - mean * mean);
    float delta = fmaxf((1.f - ss) / k, 0.f);
    float tau   = mean - sqrtf(delta);

    unsigned sup = __ballot_sync(FULL, tau <= zs);
    int kstar = __popc(sup) - 1;
    float tau_star = __shfl_sync(FULL, tau, kstar);
    float p = fmaxf(z - tau_star, 0.f);
    return p * p;
}

// ---------------- weight refill into registers (16 float4 per warp) ----------
__device__ __forceinline__ void load_w(float4* wreg, const float* __restrict__ Wp,
                                       int wid, int lane, int dbase) {
    const float4* W4 = reinterpret_cast<const float4*>(Wp)
                       + (size_t)(wid * 8) * DIMN + dbase + lane;
#pragma unroll
    for (int i = 0; i < 8; ++i) {
        wreg[i]     = __ldg(W4 + (size_t)i * DIMN);
        wreg[8 + i] = __ldg(W4 + (size_t)i * DIMN + 32);
    }
}

// ---------------- GEMV partials from register weights ----------------
// 16 warps = 16 k-segments of 32; lane covers d=lane and d=lane+32; 4 batches
__device__ __forceinline__ void gemv16_reg(const float4* __restrict__ wreg,
                                           const float4* __restrict__ xw4, // [4][128]
                                           float* __restrict__ part,
                                           int wid, int lane) {
    float a0 = 0.f, a1 = 0.f, a2 = 0.f, a3 = 0.f;
    float b0 = 0.f, b1 = 0.f, b2 = 0.f, b3 = 0.f;
#pragma unroll
    for (int i = 0; i < 8; ++i) {
        float4 w0 = wreg[i];
        float4 w1 = wreg[8 + i];
        float4 k0 = xw4[0 * 128 + wid * 8 + i];
        float4 k1 = xw4[1 * 128 + wid * 8 + i];
        float4 k2 = xw4[2 * 128 + wid * 8 + i];
        float4 k3 = xw4[3 * 128 + wid * 8 + i];
        a0 += w0.x * k0.x + w0.y * k0.y + w0.z * k0.z + w0.w * k0.w;
        a1 += w0.x * k1.x + w0.y * k1.y + w0.z * k1.z + w0.w * k1.w;
        a2 += w0.x * k2.x + w0.y * k2.y + w0.z * k2.z + w0.w * k2.w;
        a3 += w0.x * k3.x + w0.y * k3.y + w0.z * k3.z + w0.w * k3.w;
        b0 += w1.x * k0.x + w1.y * k0.y + w1.z * k0.z + w1.w * k0.w;
        b1 += w1.x * k1.x + w1.y * k1.y + w1.z * k1.z + w1.w * k1.w;
        b2 += w1.x * k2.x + w1.y * k2.y + w1.z * k2.z + w1.w * k2.w;
        b3 += w1.x * k3.x + w1.y * k3.y + w1.z * k3.z + w1.w * k3.w;
    }
    float* pp = part + wid * 256 + lane;
    pp[0]   = a0;  pp[64]  = a1;  pp[128] = a2;  pp[192] = a3;
    pp[32]  = b0;  pp[96]  = b1;  pp[160] = b2;  pp[224] = b3;
}

// ---------------- SMEM float offsets ----------------
#define SM_PART   0       // [16][4][64]          4096
#define SM_XW     4096    // [2][4][512]          4096
#define SM_WVEC   8192    // [4][64]              256
#define SM_COEFA  8448    // [4][32]              128
#define SM_COEFB  8576    // [4][32]              128
#define SM_SORT   8704    // [4][32]              128
#define SM_TAPE   8832    // [4][32][65]          8320
#define SM_XC     17152   // [2][8][4][130]       8320
#define SM_MBARB  25472   // u64
#define SM_MBARC  25474   // u64
#define SM_FLOATS 25476

// ---------------- persistent recurrence ----------------
__global__ void __launch_bounds__(NTHR, 1) __cluster_dims__(RANKS, 1, 1)
recur9(const float* __restrict__ tape0,
       const float* __restrict__ work0,
       float* __restrict__ out_hseq,
       float* __restrict__ out_tape,
       float* __restrict__ out_hlast)
{
    extern __shared__ float sm[];
    float* part_h = sm + SM_PART;          // reused for both GEMVs? no: see below
    float* xw     = sm + SM_XW;
    float* wvec   = sm + SM_WVEC;
    float* coefA  = sm + SM_COEFA;
    float* coefB  = sm + SM_COEFB;
    float* sortb  = sm + SM_SORT;
    float* tape   = sm + SM_TAPE;
    float* xc     = sm + SM_XC;
    float* part   = part_h;                // single part buffer (phases are serialized)

    const int tid  = threadIdx.x;
    const int lane = tid & 31;
    const int wid  = tid >> 5;
    const int rk   = blockIdx.x & (RANKS - 1);
    const int bg   = blockIdx.x >> 3;
    const int b0   = bg * BPC;
    const int dbase = rk * DCH;

    const uint32_t sbase = smem_u32(sm);
    const uint32_t a_xw  = sbase + SM_XW * 4u;
    const uint32_t a_xc  = sbase + SM_XC * 4u;
    const uint32_t a_mbB = sbase + SM_MBARB * 4u;
    const uint32_t a_mbC = sbase + SM_MBARC * 4u;

    if (tid == 0) {
        mbar_init(a_mbB, RANKS);
        mbar_init(a_mbC, RANKS);
    }

    // ---- prologue loads ----
    for (int i = tid; i < BPC * NSLOT * DCH; i += NTHR) {
        int b = i >> 11;
        int n = (i >> 6) & 31;
        int d = i & 63;
        tape[(b * NSLOT + n) * 65 + d] =
            tape0[((size_t)(b0 + b) * NSLOT + n) * DIMN + dbase + d];
    }
    for (int i = tid; i < BPC * DIMN; i += NTHR) {
        int b = i >> 9;
        int k = i & 511;
        xw[b * DIMN + k] = work0[(size_t)(b0 + b) * DIMN + k];
    }
    __syncthreads();
    cluster_sync_();

    const float invsd = 0.044194173824159216f;  // 1/sqrt(512)

    // weight registers: start holding W_h slice
    float4 wreg[16];
    load_w(wreg, g_WhP, wid, lane, dbase);

    // ---- initial read-scores exchange (parity 0) ----
    if (wid < BPC) {
        const int b = wid;
        const float* tr = tape + (b * NSLOT + lane) * 65;
        const float* wk = xw + b * DIMN + dbase;
        float s = 0.f;
#pragma unroll
        for (int d = 0; d < DCH; ++d) s += tr[d] * wk[d];
        uint32_t off = a_xc + (unsigned)(rk * 264 + b * 66 + 2 * lane) * 4u;
#pragma unroll
        for (int p = 0; p < RANKS; ++p) sts_cluster_f32(mapa_rank(off, p), s);
    }
    __syncthreads();
    if (tid == 0) {
#pragma unroll
        for (int p = 0; p < RANKS; ++p) mbar_arrive_cl(mapa_rank(a_mbC, p));
    }
    mbar_wait_parity_cl(a_mbC, 0u);
    if (wid < BPC) {
        const int b = wid;
        float s = 0.f;
#pragma unroll
        for (int r = 0; r < RANKS; ++r) s += xc[r * 264 + b * 66 + 2 * lane];
        coefA[b * 32 + lane] = entmax_coef(s * invsd, sortb + b * 32, lane);
    }

    // initial pre prefetch (t=0)
    float pre_reg = 0.f;
    if (tid < 256) {
        const int b = tid >> 6, d = tid & 63;
        pre_reg = __ldcs(&g_pre[((size_t)(b0 + b) * TSTEPS) * DIMN + dbase + d]);
    }
    __syncthreads();

    for (int t = 0; t < TSTEPS; ++t) {
        const int oldi = t & 1;
        const int ni   = oldi ^ 1;
        const int cp   = (t + 1) & 1;   // C exchange parity
        const int bp   = t & 1;         // B exchange parity

        // ---- phase A: W_h GEMV partials from registers; refill wreg <- W_w ----
        gemv16_reg(wreg, reinterpret_cast<const float4*>(xw + oldi * 2048),
                   part, wid, lane);
        load_w(wreg, g_WwP, wid, lane, dbase);   // latency covered by finish-h + exchange
        __syncthreads();

        // ---- finish h(t): tid<256 (b=tid>>6, d=tid&63); prefetch pre(t+1) ----
        if (tid < 256) {
            const int b = tid >> 6, d = tid & 63;
            float acc = pre_reg;
#pragma unroll
            for (int s = 0; s < 16; ++s) acc += part[s * 256 + b * 64 + d];
            const float* tr = tape + b * NSLOT * 65 + d;
            const float* cf = coefA + b * 32;
#pragma unroll 8
            for (int n = 0; n < NSLOT; ++n) acc += cf[n] * tr[n * 65];
            float h = tanhf(acc);
            __stcs(&out_hseq[((size_t)(b0 + b) * TSTEPS + t) * DIMN + dbase + d], h);
            uint32_t off = a_xw + (unsigned)(ni * 2048 + b * DIMN + dbase + d) * 4u;
#pragma unroll
            for (int p = 0; p < RANKS; ++p) sts_cluster_f32(mapa_rank(off, p), h);
            int tn = (t + 1 < TSTEPS) ? t + 1 : t;
            pre_reg = __ldcs(&g_pre[((size_t)(b0 + b) * TSTEPS + tn) * DIMN + dbase + d]);
        }
        __syncthreads();
        if (tid == 0) {
#pragma unroll
            for (int p = 0; p < RANKS; ++p) mbar_arrive_cl(mapa_rank(a_mbB, p));
        }
        mbar_wait_parity_cl(a_mbB, (uint32_t)bp);

        // ---- phase B: W_w GEMV partials from registers; refill wreg <- W_h ----
        gemv16_reg(wreg, reinterpret_cast<const float4*>(xw + ni * 2048),
                   part, wid, lane);
        load_w(wreg, g_WhP, wid, lane, dbase);   // latency covered by scores + exchange C
        __syncthreads();

        // ---- reduce wvec (tid<256) ----
        if (tid < 256) {
            const int b = tid >> 6, d = tid & 63;
            float acc = 0.f;
#pragma unroll
            for (int s = 0; s < 16; ++s) acc += part[s * 256 + b * 64 + d];
            wvec[b * 64 + d] = acc;
        }
        __syncthreads();

        // ---- scores: warps 0-3 (sA,sB) 64-d dots; warps 4-7 (sC) ----
        if (wid < BPC) {
            const int b = wid;
            const float* tr = tape + (b * NSLOT + lane) * 65;
            const float* wv = wvec + b * 64;
            const float* hh = xw + ni * 2048 + b * DIMN + dbase;
            float sA = 0.f, sB = 0.f;
#pragma unroll
            for (int d = 0; d < DCH; ++d) {
                float tv = tr[d];
                sA += tv * wv[d];
                sB += tv * hh[d];
            }
            uint32_t off = a_xc + (unsigned)(cp * 2112 + rk * 264 + b * 66 + 2 * lane) * 4u;
#pragma unroll
            for (int p = 0; p < RANKS; ++p) sts_cluster_f32x2(mapa_rank(off, p), sA, sB);
        } else if (wid < 8) {
            const int b = wid - 4;
            const float* hh = xw + ni * 2048 + b * DIMN + dbase;
            float v = wvec[b * 64 + lane] * hh[lane]
                    + wvec[b * 64 + 32 + lane] * hh[32 + lane];
#pragma unroll
            for (int o = 16; o > 0; o >>= 1) v += __shfl_xor_sync(0xffffffffu, v, o);
            if (lane == 0) {
                uint32_t off = a_xc + (unsigned)(cp * 2112 + rk * 264 + b * 66 + 64) * 4u;
#pragma unroll
                for (int p = 0; p < RANKS; ++p) sts_cluster_f32(mapa_rank(off, p), v);
            }
        }
        __syncthreads();
        if (tid == 0) {
#pragma unroll
            for (int p = 0; p < RANKS; ++p) mbar_arrive_cl(mapa_rank(a_mbC, p));
        }
        mbar_wait_parity_cl(a_mbC, (uint32_t)cp);

        // ---- D: reduce; beta = entmax(sA); alpha(t+1) via score recurrence ----
        if (wid < BPC) {
            const int b = wid;
            const float* base = xc + cp * 2112 + b * 66;
            float sA = 0.f, sB = 0.f, sC = 0.f;
#pragma unroll
            for (int r = 0; r < RANKS; ++r) {
                float2 pr = *reinterpret_cast<const float2*>(base + r * 264 + 2 * lane);
                sA += pr.x;
                sB += pr.y;
                sC += base[r * 264 + 64];
            }
            float beta = entmax_coef(sA * invsd, sortb + b * 32, lane);
            coefB[b * 32 + lane] = beta;
            float rnext = ((1.f - beta) * sB + beta * sC) * invsd;
            coefA[b * 32 + lane] = entmax_coef(rnext, sortb + b * 32, lane);
        }
        __syncthreads();

        // ---- E: tape convex update (16 warps: b, 8-slot group) ----
        {
            const int b = wid & 3;
            const int n0 = (wid >> 2) * 8;
            const float* wv = wvec + b * 64;
            const float* cf = coefB + b * 32 + n0;
            float* tb = tape + (b * NSLOT + n0) * 65;
#pragma unroll
            for (int n = 0; n < 8; ++n) {
                float bt = cf[n];
                float omb = 1.f - bt;
                float* row = tb + n * 65;
                row[lane]      = row[lane]      * omb + bt * wv[lane];
                row[lane + 32] = row[lane + 32] * omb + bt * wv[lane + 32];
            }
        }
        __syncthreads();
    }

    // ---- final outputs ----
    for (int i = tid; i < BPC * NSLOT * DCH; i += NTHR) {
        int b = i >> 11;
        int n = (i >> 6) & 31;
        int d = i & 63;
        out_tape[((size_t)(b0 + b) * NSLOT + n) * DIMN + dbase + d] =
            tape[(b * NSLOT + n) * 65 + d];
    }
    if (tid < 256) {
        const int b = tid >> 6, d = tid & 63;
        // h(2047): ni at t=2047 is 0
        out_hlast[(size_t)(b0 + b) * DIMN + dbase + d] = xw[b * DIMN + dbase + d];
    }
    cluster_sync_();
}

// ---------------- launch ----------------
extern "C" void kernel_launch(void* const* d_in, const int* in_sizes, int n_in,
                              void* d_out, int out_size) {
    const float* x     = (const float*)d_in[0];
    const float* tape0 = (const float*)d_in[1];
    const float* work0 = (const float*)d_in[2];
    const float* Wh    = (const float*)d_in[3];
    const float* Wx    = (const float*)d_in[4];
    const float* bh    = (const float*)d_in[5];
    const float* Ww    = (const float*)d_in[6];

    float* out       = (float*)d_out;
    float* out_hseq  = out;
    float* out_tape  = out + (size_t)BATCH * TSTEPS * DIMN;
    float* out_hlast = out_tape + (size_t)BATCH * NSLOT * DIMN;

    dummy_k<<<1, 32>>>();   // shifts ncu -s 5 capture onto recur9

    pack_weights<<<(DIMN * DIMN + 511) / 512, 512>>>(Wh, Ww);

    dim3 ggrid(DIMN / 64, (BATCH * TSTEPS) / 128);
    gemm_pre<<<ggrid, 256>>>(x, Wx, bh);

    const int smem_bytes = SM_FLOATS * 4 + 16;
    cudaFuncSetAttribute(recur9, cudaFuncAttributeMaxDynamicSharedMemorySize, smem_bytes);
    recur9<<<(BATCH / BPC) * RANKS, NTHR, smem_bytes>>>(
        tape0, work0, out_hseq, out_tape, out_hlast);
}